// round 5
// baseline (speedup 1.0000x reference)
#include <cuda_runtime.h>
#include <cuda_bf16.h>

// CropAndResize: image [8,256,64,64] f32 NCHW, boxes [1000,4] f32 (y1,x1,y2,x2),
// box_ind [1000] i32. Output [1000,256,14,14] f32, TF-style bilinear,
// extrapolation_value = 0 for out-of-bounds sample coordinates.
//
// R4: smem rect staging. One block = (box, 8 channels). Per channel: stage the
// input sub-rect covering all taps with coalesced LDG, then bilinear taps are
// LDS. Kills the scattered-gather L1 path that bounded R1/R3 at ~150+ us.

namespace {
constexpr int C       = 256;
constexpr int HW      = 64 * 64;
constexpr int CROP_W  = 14;
constexpr int PIX     = 196;
constexpr int CG      = 8;      // channels per block
constexpr int THREADS = 256;
constexpr int SMEM_EL = 64 * 65;  // worst case: 64 rows, stride 65 (odd)
}

__global__ __launch_bounds__(THREADS)
void crop_resize_kernel(const float* __restrict__ img,
                        const float4* __restrict__ boxes,
                        const int* __restrict__ box_ind,
                        float* __restrict__ out)
{
    __shared__ float tile[SMEM_EL];

    int tid = threadIdx.x;
    int blk = blockIdx.x;            // blk = box * (C/CG) + group
    int box = blk >> 5;              // / 32
    int cg  = blk & 31;
    int c0  = cg * CG;

    float4 bb = boxes[box];          // y1, x1, y2, x2 (uniform)
    int    b  = __ldg(box_ind + box);

    float hs = ((bb.z - bb.x) * 63.0f) / 13.0f;
    float ws = ((bb.w - bb.y) * 63.0f) / 13.0f;
    float ybase = bb.x * 63.0f;
    float xbase = bb.y * 63.0f;

    // ---- uniform rect bounds covering all (clamped) tap indices ----
    float ye = ybase + 13.0f * hs;
    float xe = xbase + 13.0f * ws;
    float ymin = fminf(ybase, ye), ymax = fmaxf(ybase, ye);
    float xmin = fminf(xbase, xe), xmax = fmaxf(xbase, xe);
    int rmin = min(max(__float2int_rd(ymin), 0), 63);
    int rmax = min(max(__float2int_rd(ymax) + 1, 0), 63);
    int cmin = min(max(__float2int_rd(xmin), 0), 63);
    int cmax = min(max(__float2int_rd(xmax) + 1, 0), 63);
    int nr = rmax - rmin + 1;
    int nc = cmax - cmin + 1;
    int s  = nc | 1;                 // odd stride -> conflict-friendly banks

    // ---- per-pixel metadata, computed once, reused for all CG channels ----
    int  otl = 0, otr = 0, obl = 0, obr = 0;
    float xl = 0.0f, yl = 0.0f;
    bool oob = false;
    if (tid < PIX) {
        int iy = tid / CROP_W;
        int ix = tid - iy * CROP_W;

        float in_y = ybase + (float)iy * hs;
        float in_x = xbase + (float)ix * ws;

        oob = (in_y < 0.0f) | (in_y > 63.0f) | (in_x < 0.0f) | (in_x > 63.0f);

        float tf = floorf(in_y);
        float lf = floorf(in_x);
        yl = in_y - tf;
        xl = in_x - lf;

        int ti = min(max((int)tf, 0), 63);
        int bi = min(max((int)tf + 1, 0), 63);
        int li = min(max((int)lf, 0), 63);
        int ri = min(max((int)lf + 1, 0), 63);

        otl = (ti - rmin) * s + (li - cmin);
        otr = (ti - rmin) * s + (ri - cmin);
        obl = (bi - rmin) * s + (li - cmin);
        obr = (bi - rmin) * s + (ri - cmin);
    }

    int tx = tid & 31;               // staging: lanes -> consecutive cols
    int ty = tid >> 5;               // 8 row-walkers

    const float* __restrict__ plane = img + ((long)b * C + c0) * HW;
    long obase = ((long)box * C + c0) * PIX + tid;

    #pragma unroll 1
    for (int cc = 0; cc < CG; ++cc) {
        __syncthreads();             // prior channel's taps done before restage
        // ---- coalesced staging of rect [rmin..rmax] x [cmin..cmax] ----
        for (int r = ty; r < nr; r += 8) {
            const float* src = plane + (rmin + r) * 64 + cmin;
            float* dst = tile + r * s;
            for (int col = tx; col < nc; col += 32)
                dst[col] = __ldg(src + col);
        }
        __syncthreads();
        // ---- bilinear taps from smem ----
        if (tid < PIX) {
            float tl = tile[otl];
            float tr = tile[otr];
            float bl = tile[obl];
            float br = tile[obr];
            float top = tl + (tr - tl) * xl;
            float bot = bl + (br - bl) * xl;
            float v   = top + (bot - top) * yl;
            out[obase + (long)cc * PIX] = oob ? 0.0f : v;
        }
        plane += HW;
    }
}

extern "C" void kernel_launch(void* const* d_in, const int* in_sizes, int n_in,
                              void* d_out, int out_size)
{
    const float*  img     = (const float*)d_in[0];
    const float4* boxes   = (const float4*)d_in[1];
    const int*    box_ind = (const int*)d_in[2];
    float*        out     = (float*)d_out;

    int n_boxes = in_sizes[2];               // 1000
    int blocks  = n_boxes * (C / CG);        // 32,000 blocks

    crop_resize_kernel<<<blocks, THREADS>>>(img, boxes, box_ind, out);
}

// round 7
// speedup vs baseline: 2.7487x; 2.7487x over previous
#include <cuda_runtime.h>
#include <cuda_bf16.h>

// CropAndResize: image [8,256,64,64] f32 NCHW, boxes [1000,4] f32 (y1,x1,y2,x2),
// box_ind [1000] i32. Output [1000,256,14,14] f32, TF-style bilinear,
// extrapolation_value = 0 for OOB sample coordinates.
//
// R5: two-kernel NHWC strategy.
//  K1: transpose image NCHW -> NHWC scratch (channel contiguous).
//  K2: warp lanes = 32 consecutive channels, so every bilinear tap is ONE
//      coalesced 128B line per warp (1 L1 wavefront) instead of a scattered
//      gather. Pixel meta (tap offsets/weights) precomputed once per block.
//      Results staged in smem [32][196] whose linear layout equals the NCHW
//      output layout -> straight coalesced dump.

namespace {
constexpr int C       = 256;
constexpr int H       = 64;
constexpr int W       = 64;
constexpr int HW      = H * W;           // 4096
constexpr int PLANE   = HW * C;          // 1,048,576 elems per batch (NHWC)
constexpr int CROP_W  = 14;
constexpr int PIX     = 196;
constexpr int CHG     = 32;              // channels per block
constexpr int NGRP    = C / CHG;         // 8
constexpr int PITCH   = 197;             // conflict-free smem pitch
}

__device__ float g_imgT[8 * PLANE];      // NHWC scratch: [b][y*64+x][c]

// ---------------- K1: NCHW -> NHWC transpose (per batch: [256][4096] -> [4096][256])
__global__ __launch_bounds__(256)
void transpose_kernel(const float* __restrict__ img)
{
    __shared__ float t[32][33];
    int b  = blockIdx.z;
    int tx = threadIdx.x, ty = threadIdx.y;

    const float* src = img   + (long)b * PLANE;
    float*       dst = g_imgT + (long)b * PLANE;

    int x = blockIdx.x * 32 + tx;        // yx coord (coalesced read axis)
    int c = blockIdx.y * 32 + ty;        // channel

    #pragma unroll
    for (int j = 0; j < 32; j += 8)
        t[ty + j][tx] = src[(long)(c + j) * HW + x];

    __syncthreads();

    int xo = blockIdx.y * 32 + tx;       // channel (coalesced write axis)
    int yo = blockIdx.x * 32 + ty;       // yx

    #pragma unroll
    for (int j = 0; j < 32; j += 8)
        dst[(long)(yo + j) * C + xo] = t[tx][ty + j];
}

// ---------------- K2: crop & resize from NHWC
__global__ __launch_bounds__(256)
void crop_resize_kernel(const float4* __restrict__ boxes,
                        const int* __restrict__ box_ind,
                        float* __restrict__ out)
{
    __shared__ int4   s_off[PIX];        // tap element offsets (yx*256)
    __shared__ float4 s_wt[PIX];         // xl, yl, mask, -
    __shared__ float  s_tile[CHG * PITCH];

    int tid = threadIdx.x;
    int blk = blockIdx.x;                // box * 8 + chgrp
    int box = blk >> 3;
    int c0  = (blk & 7) * CHG;

    float4 bb = boxes[box];              // y1, x1, y2, x2 (uniform)
    int    b  = __ldg(box_ind + box);

    if (tid < PIX) {
        float hs = ((bb.z - bb.x) * 63.0f) / 13.0f;
        float ws = ((bb.w - bb.y) * 63.0f) / 13.0f;
        float ybase = bb.x * 63.0f;
        float xbase = bb.y * 63.0f;

        int iy = tid / CROP_W;
        int ix = tid - iy * CROP_W;

        float in_y = ybase + (float)iy * hs;
        float in_x = xbase + (float)ix * ws;

        bool oob = (in_y < 0.0f) | (in_y > 63.0f) |
                   (in_x < 0.0f) | (in_x > 63.0f);

        float tf = floorf(in_y);
        float lf = floorf(in_x);
        float yl = in_y - tf;
        float xl = in_x - lf;

        int ti = min(max((int)tf, 0), 63);
        int bi = min(max((int)tf + 1, 0), 63);
        int li = min(max((int)lf, 0), 63);
        int ri = min(max((int)lf + 1, 0), 63);

        s_off[tid] = make_int4((ti * W + li) * C, (ti * W + ri) * C,
                               (bi * W + li) * C, (bi * W + ri) * C);
        s_wt[tid]  = make_float4(xl, yl, oob ? 0.0f : 1.0f, 0.0f);
    }
    __syncthreads();

    int lane  = tid & 31;                // channel within group
    int slice = tid >> 5;                // pixel slice (8 warps)

    const float* __restrict__ base = g_imgT + (long)b * PLANE + c0 + lane;
    float* trow = s_tile + lane * PITCH;

    #pragma unroll 1
    for (int p = slice; p < PIX; p += 8) {
        int4   o = s_off[p];             // broadcast LDS
        float4 w = s_wt[p];

        float tl = __ldg(base + o.x);    // each: 32 consecutive ch = 1 line
        float tr = __ldg(base + o.y);
        float bl = __ldg(base + o.z);
        float br = __ldg(base + o.w);

        float top = tl + (tr - tl) * w.x;
        float bot = bl + (br - bl) * w.x;
        float v   = (top + (bot - top) * w.y) * w.z;

        trow[p] = v;
    }
    __syncthreads();

    // dump: smem [c][p] -> out[(box*256 + c0 + c)*196 + p], linear & coalesced
    float* __restrict__ dst = out + ((long)box * C + c0) * PIX;
    int c = (tid >= PIX) ? 1 : 0;
    int p = tid - c * PIX;
    #pragma unroll 1
    for (int i = tid; i < CHG * PIX; i += 256) {
        dst[i] = s_tile[c * PITCH + p];
        p += 60; c += 1;                 // advance by 256 = 196 + 60
        if (p >= PIX) { p -= PIX; c += 1; }
    }
}

extern "C" void kernel_launch(void* const* d_in, const int* in_sizes, int n_in,
                              void* d_out, int out_size)
{
    const float*  img     = (const float*)d_in[0];
    const float4* boxes   = (const float4*)d_in[1];
    const int*    box_ind = (const int*)d_in[2];
    float*        out     = (float*)d_out;

    int n_boxes = in_sizes[2];                        // 1000

    dim3 tgrid(HW / 32, C / 32, 8);                   // 128 x 8 x 8
    dim3 tblk(32, 8);
    transpose_kernel<<<tgrid, tblk>>>(img);

    int blocks = n_boxes * NGRP;                      // 8000
    crop_resize_kernel<<<blocks, 256>>>(boxes, box_ind, out);
}

// round 8
// speedup vs baseline: 3.3041x; 1.2020x over previous
#include <cuda_runtime.h>
#include <cuda_bf16.h>

// CropAndResize: image [8,256,64,64] f32 NCHW, boxes [1000,4] f32 (y1,x1,y2,x2),
// box_ind [1000] i32. Output [1000,256,14,14] f32, TF-style bilinear,
// extrapolation_value = 0 for OOB sample coordinates.
//
// R6: NHWC strategy, float2 lanes.
//  K1: transpose image NCHW -> NHWC scratch (channel contiguous).
//  K2: warp = 64 consecutive channels (float2 per lane); every bilinear tap is
//      one LDG.64 warp instruction (256B, fully used). Pixel meta precomputed.
//      Results staged pixel-major in smem [196][66] (aligned float2 STS,
//      conflict-free writes), then dumped coalesced in NCHW order.

namespace {
constexpr int C       = 256;
constexpr int H       = 64;
constexpr int W       = 64;
constexpr int HW      = H * W;           // 4096
constexpr int PLANE   = HW * C;          // per-batch elems (NHWC)
constexpr int CROP_W  = 14;
constexpr int PIX     = 196;
constexpr int CHG     = 64;              // channels per block
constexpr int NGRP    = C / CHG;         // 4
constexpr int BLOCK   = 512;             // 16 warps
constexpr int PITCH   = CHG + 2;         // 66: even (8B-aligned float2), bank-stride 2
constexpr int TILE_EL = PIX * PITCH;     // 12936 floats
}

__device__ float g_imgT[8 * PLANE];      // NHWC scratch: [b][y*64+x][c]

// ---------------- K1: NCHW -> NHWC transpose
__global__ __launch_bounds__(256)
void transpose_kernel(const float* __restrict__ img)
{
    __shared__ float t[32][33];
    int b  = blockIdx.z;
    int tx = threadIdx.x, ty = threadIdx.y;

    const float* src = img    + (long)b * PLANE;
    float*       dst = g_imgT + (long)b * PLANE;

    int x = blockIdx.x * 32 + tx;        // yx (coalesced read axis)
    int c = blockIdx.y * 32 + ty;        // channel

    #pragma unroll
    for (int j = 0; j < 32; j += 8)
        t[ty + j][tx] = src[(long)(c + j) * HW + x];

    __syncthreads();

    int xo = blockIdx.y * 32 + tx;       // channel (coalesced write axis)
    int yo = blockIdx.x * 32 + ty;       // yx

    #pragma unroll
    for (int j = 0; j < 32; j += 8)
        dst[(long)(yo + j) * C + xo] = t[tx][ty + j];
}

// ---------------- K2: crop & resize from NHWC, float2 lanes
__global__ __launch_bounds__(BLOCK)
void crop_resize_kernel(const float4* __restrict__ boxes,
                        const int* __restrict__ box_ind,
                        float* __restrict__ out)
{
    extern __shared__ float smem[];
    float* s_tile = smem;                               // [196][66]
    int4*  s_off  = (int4*)(smem + TILE_EL);            // [196]
    float4* s_wt  = (float4*)(s_off + PIX);             // [196]

    int tid = threadIdx.x;
    int blk = blockIdx.x;                // box * NGRP + chgrp
    int box = blk >> 2;
    int c0  = (blk & 3) * CHG;

    float4 bb = boxes[box];              // y1, x1, y2, x2 (uniform)
    int    b  = __ldg(box_ind + box);

    if (tid < PIX) {
        float hs = ((bb.z - bb.x) * 63.0f) / 13.0f;
        float ws = ((bb.w - bb.y) * 63.0f) / 13.0f;
        float ybase = bb.x * 63.0f;
        float xbase = bb.y * 63.0f;

        int iy = tid / CROP_W;
        int ix = tid - iy * CROP_W;

        float in_y = ybase + (float)iy * hs;
        float in_x = xbase + (float)ix * ws;

        bool oob = (in_y < 0.0f) | (in_y > 63.0f) |
                   (in_x < 0.0f) | (in_x > 63.0f);

        float tf = floorf(in_y);
        float lf = floorf(in_x);
        float yl = in_y - tf;
        float xl = in_x - lf;

        int ti = min(max((int)tf, 0), 63);
        int bi = min(max((int)tf + 1, 0), 63);
        int li = min(max((int)lf, 0), 63);
        int ri = min(max((int)lf + 1, 0), 63);

        s_off[tid] = make_int4((ti * W + li) * C, (ti * W + ri) * C,
                               (bi * W + li) * C, (bi * W + ri) * C);
        s_wt[tid]  = make_float4(xl, yl, oob ? 0.0f : 1.0f, 0.0f);
    }
    __syncthreads();

    int lane  = tid & 31;                // 2 channels per lane
    int slice = tid >> 5;                // 16 pixel slices

    const float2* __restrict__ base =
        (const float2*)(g_imgT + (long)b * PLANE + c0) + lane;

    #pragma unroll 1
    for (int p = slice; p < PIX; p += 16) {
        int4   o = s_off[p];             // broadcast LDS
        float4 w = s_wt[p];

        float2 tl = __ldg(base + (o.x >> 1));   // 64 consecutive ch per warp
        float2 tr = __ldg(base + (o.y >> 1));
        float2 bl = __ldg(base + (o.z >> 1));
        float2 br = __ldg(base + (o.w >> 1));

        float2 v;
        {
            float top = tl.x + (tr.x - tl.x) * w.x;
            float bot = bl.x + (br.x - bl.x) * w.x;
            v.x = (top + (bot - top) * w.y) * w.z;
        }
        {
            float top = tl.y + (tr.y - tl.y) * w.x;
            float bot = bl.y + (br.y - bl.y) * w.x;
            v.y = (top + (bot - top) * w.y) * w.z;
        }

        *(float2*)(s_tile + p * PITCH + 2 * lane) = v;
    }
    __syncthreads();

    // dump: smem [p][c] -> out[(box*256 + c0 + c)*196 + p], coalesced NCHW order
    float* __restrict__ dst = out + ((long)box * C + c0) * PIX;
    int c = tid / PIX;                   // 0..2 for tid < 512
    int p = tid - c * PIX;
    #pragma unroll 1
    for (int i = tid; i < CHG * PIX; i += BLOCK) {
        dst[i] = s_tile[p * PITCH + c];
        p += 120; c += 2;                // advance by 512 = 2*196 + 120
        if (p >= PIX) { p -= PIX; c += 1; }
    }
}

extern "C" void kernel_launch(void* const* d_in, const int* in_sizes, int n_in,
                              void* d_out, int out_size)
{
    const float*  img     = (const float*)d_in[0];
    const float4* boxes   = (const float4*)d_in[1];
    const int*    box_ind = (const int*)d_in[2];
    float*        out     = (float*)d_out;

    int n_boxes = in_sizes[2];                        // 1000

    dim3 tgrid(HW / 32, C / 32, 8);
    dim3 tblk(32, 8);
    transpose_kernel<<<tgrid, tblk>>>(img);

    size_t shmem = (size_t)TILE_EL * 4 + (size_t)PIX * (16 + 16);  // ~58 KB
    cudaFuncSetAttribute(crop_resize_kernel,
                         cudaFuncAttributeMaxDynamicSharedMemorySize, (int)shmem);

    int blocks = n_boxes * NGRP;                      // 4000
    crop_resize_kernel<<<blocks, BLOCK, shmem>>>(boxes, box_ind, out);
}

// round 9
// speedup vs baseline: 3.3873x; 1.0252x over previous
#include <cuda_runtime.h>
#include <cuda_bf16.h>

// CropAndResize: image [8,256,64,64] f32 NCHW, boxes [1000,4] f32 (y1,x1,y2,x2),
// box_ind [1000] i32. Output [1000,256,14,14] f32, TF-style bilinear,
// extrapolation_value = 0 for OOB sample coordinates.
//
// R7: NHWC strategy, float2 lanes, occupancy push.
//  K1: transpose image NCHW -> NHWC scratch (+ zero pad page for OOB taps).
//  K2: warp = 64 consecutive channels (float2 per lane); every tap is one
//      coalesced LDG.64 warp instruction. OOB pixels redirect taps into the
//      zero page with xl=yl=0 (no mask lane). Meta trimmed to 24B/pixel ->
//      smem 56.4KB -> 4 blocks/SM (2048 threads). Results staged in smem
//      [196][66] then dumped coalesced in NCHW order.

namespace {
constexpr int C       = 256;
constexpr int H       = 64;
constexpr int W       = 64;
constexpr int HW      = H * W;           // 4096
constexpr int PLANE   = HW * C;          // per-batch elems (NHWC)
constexpr int CROP_W  = 14;
constexpr int PIX     = 196;
constexpr int CHG     = 64;              // channels per block
constexpr int NGRP    = C / CHG;         // 4
constexpr int BLOCK   = 512;             // 16 warps
constexpr int PITCH   = CHG + 2;         // 66
constexpr int TILE_EL = PIX * PITCH;     // 12936 floats
}

__device__ float g_imgT[8 * PLANE + 128];  // NHWC scratch + zero page

// ---------------- K1: NCHW -> NHWC transpose (+ zero the pad page)
__global__ __launch_bounds__(256)
void transpose_kernel(const float* __restrict__ img)
{
    __shared__ float t[32][33];
    int b  = blockIdx.z;
    int tx = threadIdx.x, ty = threadIdx.y;

    if (blockIdx.x == 0 && blockIdx.y == 0 && b == 0) {
        int id = ty * 32 + tx;
        if (id < 128) g_imgT[8 * PLANE + id] = 0.0f;
    }

    const float* src = img    + (long)b * PLANE;
    float*       dst = g_imgT + (long)b * PLANE;

    int x = blockIdx.x * 32 + tx;        // yx (coalesced read axis)
    int c = blockIdx.y * 32 + ty;        // channel

    #pragma unroll
    for (int j = 0; j < 32; j += 8)
        t[ty + j][tx] = src[(long)(c + j) * HW + x];

    __syncthreads();

    int xo = blockIdx.y * 32 + tx;       // channel (coalesced write axis)
    int yo = blockIdx.x * 32 + ty;       // yx

    #pragma unroll
    for (int j = 0; j < 32; j += 8)
        dst[(long)(yo + j) * C + xo] = t[tx][ty + j];
}

// ---------------- K2: crop & resize from NHWC, float2 lanes
__global__ __launch_bounds__(BLOCK, 4)
void crop_resize_kernel(const float4* __restrict__ boxes,
                        const int* __restrict__ box_ind,
                        float* __restrict__ out)
{
    extern __shared__ float smem[];
    float*  s_tile = smem;                               // [196][66]
    int4*   s_off  = (int4*)(smem + TILE_EL);            // [196] float2-unit offs
    float2* s_xy   = (float2*)(s_off + PIX);             // [196] xl, yl

    int tid = threadIdx.x;
    int blk = blockIdx.x;                // box * NGRP + chgrp
    int box = blk >> 2;
    int c0  = (blk & 3) * CHG;

    float4 bb = boxes[box];              // y1, x1, y2, x2 (uniform)
    int    b  = __ldg(box_ind + box);

    if (tid < PIX) {
        float hs = ((bb.z - bb.x) * 63.0f) / 13.0f;
        float ws = ((bb.w - bb.y) * 63.0f) / 13.0f;
        float ybase = bb.x * 63.0f;
        float xbase = bb.y * 63.0f;

        int iy = tid / CROP_W;
        int ix = tid - iy * CROP_W;

        float in_y = ybase + (float)iy * hs;
        float in_x = xbase + (float)ix * ws;

        bool oob = (in_y < 0.0f) | (in_y > 63.0f) |
                   (in_x < 0.0f) | (in_x > 63.0f);

        float tf = floorf(in_y);
        float lf = floorf(in_x);
        float yl = in_y - tf;
        float xl = in_x - lf;

        int ti = min(max((int)tf, 0), 63);
        int bi = min(max((int)tf + 1, 0), 63);
        int li = min(max((int)lf, 0), 63);
        int ri = min(max((int)lf + 1, 0), 63);

        if (oob) {
            // redirect all taps into the zero page; xl=yl=0 -> v = 0 exactly
            int zo = ((8 - b) * PLANE - c0) >> 1;          // float2 units
            s_off[tid] = make_int4(zo, zo, zo, zo);
            s_xy[tid]  = make_float2(0.0f, 0.0f);
        } else {
            s_off[tid] = make_int4(((ti * W + li) * C) >> 1,
                                   ((ti * W + ri) * C) >> 1,
                                   ((bi * W + li) * C) >> 1,
                                   ((bi * W + ri) * C) >> 1);
            s_xy[tid]  = make_float2(xl, yl);
        }
    }
    __syncthreads();

    int lane  = tid & 31;                // 2 channels per lane
    int slice = tid >> 5;                // 16 pixel slices

    const float2* __restrict__ base =
        (const float2*)(g_imgT + (long)b * PLANE + c0) + lane;

    #pragma unroll 1
    for (int p = slice; p < PIX; p += 16) {
        int4   o = s_off[p];             // broadcast LDS (pre-shifted)
        float2 w = s_xy[p];

        float2 tl = __ldg(base + o.x);   // 64 consecutive ch per warp
        float2 tr = __ldg(base + o.y);
        float2 bl = __ldg(base + o.z);
        float2 br = __ldg(base + o.w);

        float2 v;
        {
            float top = tl.x + (tr.x - tl.x) * w.x;
            float bot = bl.x + (br.x - bl.x) * w.x;
            v.x = top + (bot - top) * w.y;
        }
        {
            float top = tl.y + (tr.y - tl.y) * w.x;
            float bot = bl.y + (br.y - bl.y) * w.x;
            v.y = top + (bot - top) * w.y;
        }

        *(float2*)(s_tile + p * PITCH + 2 * lane) = v;
    }
    __syncthreads();

    // dump: smem [p][c] -> out[(box*256 + c0 + c)*196 + p], coalesced NCHW order
    float* __restrict__ dst = out + ((long)box * C + c0) * PIX;
    int c = tid / PIX;                   // 0..2 for tid < 512
    int p = tid - c * PIX;
    #pragma unroll 1
    for (int i = tid; i < CHG * PIX; i += BLOCK) {
        dst[i] = s_tile[p * PITCH + c];
        p += 120; c += 2;                // advance by 512 = 2*196 + 120
        if (p >= PIX) { p -= PIX; c += 1; }
    }
}

extern "C" void kernel_launch(void* const* d_in, const int* in_sizes, int n_in,
                              void* d_out, int out_size)
{
    const float*  img     = (const float*)d_in[0];
    const float4* boxes   = (const float4*)d_in[1];
    const int*    box_ind = (const int*)d_in[2];
    float*        out     = (float*)d_out;

    int n_boxes = in_sizes[2];                        // 1000

    dim3 tgrid(HW / 32, C / 32, 8);
    dim3 tblk(32, 8);
    transpose_kernel<<<tgrid, tblk>>>(img);

    size_t shmem = (size_t)TILE_EL * 4 + (size_t)PIX * (16 + 8);  // 56448 B
    cudaFuncSetAttribute(crop_resize_kernel,
                         cudaFuncAttributeMaxDynamicSharedMemorySize, (int)shmem);

    int blocks = n_boxes * NGRP;                      // 4000
    crop_resize_kernel<<<blocks, BLOCK, shmem>>>(boxes, box_ind, out);
}